// round 1
// baseline (speedup 1.0000x reference)
#include <cuda_runtime.h>
#include <math.h>

#define NQ 12
#define NST 4096
#define TPB 256
#define NB 256
#define NLAYERS 6

__device__ __forceinline__ float2 cmulc(float2 x, float2 y) {
    return make_float2(x.x * y.x - x.y * y.y, x.x * y.y + x.y * y.x);
}

// m1*v1 + m2*v2 (complex), fully FMA'd
__device__ __forceinline__ float2 cmad2(float2 m1, float2 v1, float2 m2, float2 v2) {
    float re = m1.x * v1.x;
    re = fmaf(-m1.y, v1.y, re);
    re = fmaf(m2.x, v2.x, re);
    re = fmaf(-m2.y, v2.y, re);
    float im = m1.x * v1.y;
    im = fmaf(m1.y, v1.x, im);
    im = fmaf(m2.x, v2.y, im);
    im = fmaf(m2.y, v2.x, im);
    return make_float2(re, im);
}

__device__ __forceinline__ float gelu_f(float x) {
    return 0.5f * x * (1.0f + erff(x * 0.7071067811865476f));
}

// Composed CNOT-ring permutation: dst index for src index (forward scatter),
// for the chain CNOT(0,1),CNOT(1,2),...,CNOT(10,11),CNOT(11,0).
// Qubit w lives at bit position (11-w).
__device__ __forceinline__ int permdst(int idx) {
    int y = idx;
    y ^= y >> 1; y ^= y >> 2; y ^= y >> 4; y ^= y >> 8;
    // bits 0..10 of dst = y bits 0..10 ; bit 11 = (parity of all bits) ^ (src bit 11)
    return (y & 0x7FF) | (((y ^ (idx >> 11)) & 1) << 11);
}

__global__ void __launch_bounds__(TPB)
qpu_kernel(const float* __restrict__ x,
           const float* __restrict__ W1, const float* __restrict__ b1,
           const float* __restrict__ g_ln, const float* __restrict__ b_ln,
           const float* __restrict__ W2, const float* __restrict__ b2,
           const float* __restrict__ W3, const float* __restrict__ b3,
           const float* __restrict__ qw,
           const float* __restrict__ W4, const float* __restrict__ b4,
           const float* __restrict__ W5, const float* __restrict__ b5,
           float* __restrict__ out)
{
    extern __shared__ float2 sbuf[];   // 2 * 4096 float2 = 64 KB (ping-pong state)
    __shared__ __align__(16) float xrow[256];
    __shared__ __align__(16) float h1s[128];
    __shared__ __align__(16) float hns[128];
    __shared__ __align__(16) float h2s[64];
    __shared__ float2 Um[NLAYERS][NQ][4];   // m00,m01,m10,m11
    __shared__ float2 v0s[NQ], v1s[NQ];     // initial per-qubit product-state vectors
    __shared__ float cqs[NQ], sqs[NQ];      // re-upload RY half-angle cos/sin
    __shared__ float red0[8], red1[8];
    __shared__ float stats[2];
    __shared__ float wz[8][3];
    __shared__ float qv[3];
    __shared__ float h4s[32];

    const int tid = threadIdx.x;
    const int bidx = blockIdx.x;
    const int lane = tid & 31, wid = tid >> 5;

    xrow[tid] = x[bidx * 256 + tid];

    // ---- per-(layer,qubit) gate matrices U = RZ(w2) RY(w1) RZ(w0) ----
    if (tid < NLAYERS * NQ) {
        float w0 = qw[tid * 3 + 0], w1 = qw[tid * 3 + 1], w2 = qw[tid * 3 + 2];
        float sh, ch; sincosf(0.5f * w1, &sh, &ch);
        float sa, ca; sincosf(0.5f * (w0 + w2), &sa, &ca);
        float sb, cb; sincosf(0.5f * (w0 - w2), &sb, &cb);
        int L = tid / NQ, q = tid % NQ;
        Um[L][q][0] = make_float2(ch * ca, -ch * sa);   // U00 = c e^{-i(w0+w2)/2}
        Um[L][q][1] = make_float2(-sh * cb, -sh * sb);  // U01 = -s e^{+i(w0-w2)/2}
        Um[L][q][2] = make_float2(sh * cb, -sh * sb);   // U10 =  s e^{-i(w0-w2)/2}
        Um[L][q][3] = make_float2(ch * ca, ch * sa);    // U11 = c e^{+i(w0+w2)/2}
    }
    __syncthreads();

    // ---- h1 = gelu(x @ W1^T + b1), 128 outputs ----
    if (tid < 128) {
        const float4* wr = (const float4*)(W1 + tid * 256);
        const float4* xr = (const float4*)xrow;
        float acc = 0.f;
        #pragma unroll 8
        for (int k = 0; k < 64; k++) {
            float4 w = wr[k], xv = xr[k];
            acc = fmaf(w.x, xv.x, acc); acc = fmaf(w.y, xv.y, acc);
            acc = fmaf(w.z, xv.z, acc); acc = fmaf(w.w, xv.w, acc);
        }
        h1s[tid] = gelu_f(acc + b1[tid]);
    }
    __syncthreads();

    // ---- layernorm over 128 ----
    {
        float v = (tid < 128) ? h1s[tid] : 0.f;
        float s = v, ss = v * v;
        #pragma unroll
        for (int o = 16; o; o >>= 1) {
            s += __shfl_xor_sync(~0u, s, o);
            ss += __shfl_xor_sync(~0u, ss, o);
        }
        if (lane == 0) { red0[wid] = s; red1[wid] = ss; }
    }
    __syncthreads();
    if (tid == 0) {
        float s = 0.f, ss = 0.f;
        #pragma unroll
        for (int w = 0; w < 8; w++) { s += red0[w]; ss += red1[w]; }
        float mu = s * (1.f / 128.f);
        float var = ss * (1.f / 128.f) - mu * mu;
        stats[0] = mu; stats[1] = rsqrtf(var + 1e-5f);
    }
    __syncthreads();
    if (tid < 128)
        hns[tid] = (h1s[tid] - stats[0]) * stats[1] * g_ln[tid] + b_ln[tid];
    __syncthreads();

    // ---- h2 = gelu(hn @ W2^T + b2), 64 outputs ----
    if (tid < 64) {
        const float4* wr = (const float4*)(W2 + tid * 128);
        const float4* hr = (const float4*)hns;
        float acc = 0.f;
        #pragma unroll 8
        for (int k = 0; k < 32; k++) {
            float4 w = wr[k], h = hr[k];
            acc = fmaf(w.x, h.x, acc); acc = fmaf(w.y, h.y, acc);
            acc = fmaf(w.z, h.z, acc); acc = fmaf(w.w, h.w, acc);
        }
        h2s[tid] = gelu_f(acc + b2[tid]);
    }
    __syncthreads();

    // ---- xq = tanh(h2 @ W3^T + b3); enc = xq*pi^2; build per-qubit init vectors ----
    if (tid < NQ) {
        const float* wr = W3 + tid * 64;
        float acc = 0.f;
        #pragma unroll
        for (int k = 0; k < 64; k++) acc = fmaf(wr[k], h2s[k], acc);
        float xqv = tanhf(acc + b3[tid]);
        float e = xqv * 9.869604401089358f;   // pi^2
        float se, ce; sincosf(0.5f * e, &se, &ce);     // RY(enc) half-angle
        float2 u00 = Um[0][tid][0], u01 = Um[0][tid][1];
        float2 u10 = Um[0][tid][2], u11 = Um[0][tid][3];
        // v = U(0,q) @ (ce, se)^T  (folds layer-0 U round into the product state)
        v0s[tid] = make_float2(u00.x * ce + u01.x * se, u00.y * ce + u01.y * se);
        v1s[tid] = make_float2(u10.x * ce + u11.x * se, u10.y * ce + u11.y * se);
        float sh, chh; sincosf(0.25f * e, &sh, &chh);  // RY(enc*0.5) half-angle
        cqs[tid] = chh; sqs[tid] = sh;
    }
    __syncthreads();

    float2* cur = sbuf;
    float2* alt = sbuf + NST;

    // ---- initial product state ----
    {
        // thread owns amplitudes idx = g*256 + tid ; tid gives bit positions 0..7
        float2 cm = (tid & 1) ? v1s[11] : v0s[11];
        #pragma unroll
        for (int p = 1; p < 8; p++) {
            float2 f = ((tid >> p) & 1) ? v1s[11 - p] : v0s[11 - p];
            cm = cmulc(cm, f);
        }
        #pragma unroll
        for (int g = 0; g < 16; g++) {
            float2 a = cm;
            #pragma unroll
            for (int p = 8; p < 12; p++) {
                float2 f = ((g >> (p - 8)) & 1) ? v1s[11 - p] : v0s[11 - p];
                a = cmulc(a, f);
            }
            cur[g * 256 + tid] = a;
        }
    }
    __syncthreads();

    // qubit-pair pass list (bit positions): hi paired with lo, each qubit once.
    const int PHI[6] = {11, 10, 9, 8, 7, 6};
    const int PLO[6] = {3, 2, 1, 0, 4, 5};

    for (int layer = 0; layer < NLAYERS; layer++) {
        // -- single-qubit gate round (layer 0 is folded into init) --
        if (layer >= 1) {
            const bool mergeRY = (layer & 1);   // re-upload after even layers merges here
            for (int ps = 0; ps < 6; ps++) {
                const int pH = PHI[ps], pL = PLO[ps];
                const int qH = 11 - pH, qL = 11 - pL;
                float2 A00 = Um[layer][qH][0], A01 = Um[layer][qH][1];
                float2 A10 = Um[layer][qH][2], A11 = Um[layer][qH][3];
                float2 B00 = Um[layer][qL][0], B01 = Um[layer][qL][1];
                float2 B10 = Um[layer][qL][2], B11 = Um[layer][qL][3];
                if (mergeRY) {
                    float cf = cqs[qH], sf = sqs[qH];
                    float2 n00 = make_float2(A00.x*cf + A01.x*sf, A00.y*cf + A01.y*sf);
                    float2 n01 = make_float2(-A00.x*sf + A01.x*cf, -A00.y*sf + A01.y*cf);
                    float2 n10 = make_float2(A10.x*cf + A11.x*sf, A10.y*cf + A11.y*sf);
                    float2 n11 = make_float2(-A10.x*sf + A11.x*cf, -A10.y*sf + A11.y*cf);
                    A00 = n00; A01 = n01; A10 = n10; A11 = n11;
                    cf = cqs[qL]; sf = sqs[qL];
                    n00 = make_float2(B00.x*cf + B01.x*sf, B00.y*cf + B01.y*sf);
                    n01 = make_float2(-B00.x*sf + B01.x*cf, -B00.y*sf + B01.y*cf);
                    n10 = make_float2(B10.x*cf + B11.x*sf, B10.y*cf + B11.y*sf);
                    n11 = make_float2(-B10.x*sf + B11.x*cf, -B10.y*sf + B11.y*cf);
                    B00 = n00; B01 = n01; B10 = n10; B11 = n11;
                }
                const int mH = 1 << pH, mL = 1 << pL;
                #pragma unroll
                for (int g = 0; g < 4; g++) {
                    int qd = tid + 256 * g;
                    int i = ((qd >> pL) << (pL + 1)) | (qd & (mL - 1));
                    i = ((i >> pH) << (pH + 1)) | (i & (mH - 1));
                    float2 a00 = cur[i],       a01 = cur[i | mL];
                    float2 a10 = cur[i | mH],  a11 = cur[i | mH | mL];
                    // apply A on the hi bit
                    float2 t00 = cmad2(A00, a00, A01, a10);
                    float2 t10 = cmad2(A10, a00, A11, a10);
                    float2 t01 = cmad2(A00, a01, A01, a11);
                    float2 t11 = cmad2(A10, a01, A11, a11);
                    // apply B on the lo bit
                    cur[i]           = cmad2(B00, t00, B01, t01);
                    cur[i | mL]      = cmad2(B10, t00, B11, t01);
                    cur[i | mH]      = cmad2(B00, t10, B01, t11);
                    cur[i | mH | mL] = cmad2(B10, t10, B11, t11);
                }
                __syncthreads();
            }
        }

        // -- CNOT-ring permutation (+ folded CZ on odd layers) --
        // Layer 5's perm is folded into measurement; its CZ is phase-only (skipped).
        if (layer < 5) {
            const bool cz = (layer & 1);
            #pragma unroll
            for (int g = 0; g < 16; g++) {
                int idx = g * 256 + tid;
                float2 a = cur[idx];
                int dst = permdst(idx);
                if (cz) {
                    // CZ pairs on qubits (0,2),(2,4),(4,6),(6,8),(8,10) -> dst bit
                    // pairs (11,9),(9,7),(7,5),(5,3),(3,1); parity of AND terms.
                    int f = __popc((dst & (dst >> 2)) & 0x2AA) & 1;
                    if (f) { a.x = -a.x; a.y = -a.y; }
                }
                alt[dst] = a;
            }
            __syncthreads();
            float2* t = cur; cur = alt; alt = t;
        }
    }

    // ---- measurement: <Z> on qubits 0,1,2 with layer-5 perm folded into indexing ----
    float z0 = 0.f, z1 = 0.f, z2 = 0.f;
    #pragma unroll
    for (int g = 0; g < 16; g++) {
        int idx = g * 256 + tid;
        float2 a = cur[idx];
        float p = a.x * a.x + a.y * a.y;
        int dst = permdst(idx);
        z0 += ((dst >> 11) & 1) ? -p : p;
        z1 += ((dst >> 10) & 1) ? -p : p;
        z2 += ((dst >> 9) & 1) ? -p : p;
    }
    #pragma unroll
    for (int o = 16; o; o >>= 1) {
        z0 += __shfl_xor_sync(~0u, z0, o);
        z1 += __shfl_xor_sync(~0u, z1, o);
        z2 += __shfl_xor_sync(~0u, z2, o);
    }
    if (lane == 0) { wz[wid][0] = z0; wz[wid][1] = z1; wz[wid][2] = z2; }
    __syncthreads();
    if (tid < 3) {
        float t = 0.f;
        #pragma unroll
        for (int w = 0; w < 8; w++) t += wz[w][tid];
        qv[tid] = t;
    }
    __syncthreads();

    // ---- head: gelu(q @ W4^T + b4) @ W5^T + b5 ----
    if (tid < 32) {
        float acc = b4[tid];
        acc = fmaf(W4[tid * 3 + 0], qv[0], acc);
        acc = fmaf(W4[tid * 3 + 1], qv[1], acc);
        acc = fmaf(W4[tid * 3 + 2], qv[2], acc);
        h4s[tid] = gelu_f(acc);
    }
    __syncthreads();
    if (tid < 64) {
        const float* wr = W5 + tid * 32;
        float acc = b5[tid];
        #pragma unroll
        for (int j = 0; j < 32; j++) acc = fmaf(wr[j], h4s[j], acc);
        out[bidx * 64 + tid] = acc;
    }
}

extern "C" void kernel_launch(void* const* d_in, const int* in_sizes, int n_in,
                              void* d_out, int out_size)
{
    const float* x    = (const float*)d_in[0];
    const float* W1   = (const float*)d_in[1];
    const float* b1   = (const float*)d_in[2];
    const float* g_ln = (const float*)d_in[3];
    const float* b_ln = (const float*)d_in[4];
    const float* W2   = (const float*)d_in[5];
    const float* b2   = (const float*)d_in[6];
    const float* W3   = (const float*)d_in[7];
    const float* b3   = (const float*)d_in[8];
    const float* qw   = (const float*)d_in[9];
    const float* W4   = (const float*)d_in[10];
    const float* b4   = (const float*)d_in[11];
    const float* W5   = (const float*)d_in[12];
    const float* b5   = (const float*)d_in[13];

    const size_t shmem = 2 * (size_t)NST * sizeof(float2);  // 64 KB ping-pong state
    cudaFuncSetAttribute(qpu_kernel, cudaFuncAttributeMaxDynamicSharedMemorySize,
                         (int)shmem);
    qpu_kernel<<<NB, TPB, shmem>>>(x, W1, b1, g_ln, b_ln, W2, b2, W3, b3, qw,
                                   W4, b4, W5, b5, (float*)d_out);
}

// round 2
// speedup vs baseline: 1.2734x; 1.2734x over previous
#include <cuda_runtime.h>
#include <math.h>

#define NQ 12
#define TPB 256
#define NB 256

__device__ __forceinline__ float2 cmulc(float2 x, float2 y) {
    return make_float2(x.x * y.x - x.y * y.y, x.x * y.y + x.y * y.x);
}

// m1*v1 + m2*v2 (complex), fully FMA'd
__device__ __forceinline__ float2 cmad2(float2 m1, float2 v1, float2 m2, float2 v2) {
    float re = m1.x * v1.x;
    re = fmaf(-m1.y, v1.y, re);
    re = fmaf(m2.x, v2.x, re);
    re = fmaf(-m2.y, v2.y, re);
    float im = m1.x * v1.y;
    im = fmaf(m1.y, v1.x, im);
    im = fmaf(m2.x, v2.y, im);
    im = fmaf(m2.y, v2.x, im);
    return make_float2(re, im);
}

__device__ __forceinline__ float gelu_f(float x) {
    return 0.5f * x * (1.0f + erff(x * 0.7071067811865476f));
}

// Composed CNOT-ring permutation (CNOT(0,1)..CNOT(10,11),CNOT(11,0)).
// Qubit w lives at bit position (11-w).
__device__ __forceinline__ int permdst(int idx) {
    int y = idx;
    y ^= y >> 1; y ^= y >> 2; y ^= y >> 4; y ^= y >> 8;
    return (y & 0x7FF) | (((y ^ (idx >> 11)) & 1) << 11);
}

// transposed layout index: i bits {0..4}=lane, {5..7}=r bits 0..2,
// {8..10}=warp, {11}=r bit 3
__device__ __forceinline__ int tix(int r, int tid) {
    return (tid & 31) | ((r & 7) << 5) | ((tid >> 5) << 8) | ((r >> 3) << 11);
}

__global__ void __launch_bounds__(TPB, 2)
qpu_kernel(const float* __restrict__ x,
           const float* __restrict__ W1, const float* __restrict__ b1,
           const float* __restrict__ g_ln, const float* __restrict__ b_ln,
           const float* __restrict__ W2, const float* __restrict__ b2,
           const float* __restrict__ W3, const float* __restrict__ b3,
           const float* __restrict__ qw,
           const float* __restrict__ W4, const float* __restrict__ b4,
           const float* __restrict__ W5, const float* __restrict__ b5,
           float* __restrict__ out)
{
    // dynamic: 2 SoA buffers, each 4096 re + 4096 im floats = 64 KB
    extern __shared__ float dsm[];
    __shared__ __align__(16) float xrow[256];
    __shared__ __align__(16) float h1s[128];
    __shared__ __align__(16) float hns[128];
    __shared__ __align__(16) float h2s[64];
    __shared__ float2 Mm[5][NQ][4];       // merged gate matrices, layers 1..5
    __shared__ float2 v0s[NQ], v1s[NQ];   // initial per-qubit product-state vectors
    __shared__ float cqs[NQ], sqs[NQ];    // re-upload RY half-angle cos/sin
    __shared__ float red0[8], red1[8];
    __shared__ float stats[2];
    __shared__ float wz[8][3];
    __shared__ float qv[3];
    __shared__ float h4s[32];

    const int tid = threadIdx.x;
    const int bidx = blockIdx.x;
    const int lane = tid & 31, wid = tid >> 5;

    xrow[tid] = x[bidx * 256 + tid];
    __syncthreads();

    // ---- h1 = gelu(x @ W1^T + b1), 128 outputs ----
    if (tid < 128) {
        const float4* wr = (const float4*)(W1 + tid * 256);
        const float4* xr = (const float4*)xrow;
        float acc0 = 0.f, acc1 = 0.f;
        #pragma unroll 8
        for (int k = 0; k < 64; k += 2) {
            float4 w = wr[k], xv = xr[k];
            acc0 = fmaf(w.x, xv.x, acc0); acc0 = fmaf(w.y, xv.y, acc0);
            acc0 = fmaf(w.z, xv.z, acc0); acc0 = fmaf(w.w, xv.w, acc0);
            float4 w2_ = wr[k + 1], xv2 = xr[k + 1];
            acc1 = fmaf(w2_.x, xv2.x, acc1); acc1 = fmaf(w2_.y, xv2.y, acc1);
            acc1 = fmaf(w2_.z, xv2.z, acc1); acc1 = fmaf(w2_.w, xv2.w, acc1);
        }
        h1s[tid] = gelu_f(acc0 + acc1 + b1[tid]);
    }
    __syncthreads();

    // ---- layernorm over 128 ----
    {
        float v = (tid < 128) ? h1s[tid] : 0.f;
        float s = v, ss = v * v;
        #pragma unroll
        for (int o = 16; o; o >>= 1) {
            s += __shfl_xor_sync(~0u, s, o);
            ss += __shfl_xor_sync(~0u, ss, o);
        }
        if (lane == 0) { red0[wid] = s; red1[wid] = ss; }
    }
    __syncthreads();
    if (tid == 0) {
        float s = 0.f, ss = 0.f;
        #pragma unroll
        for (int w = 0; w < 8; w++) { s += red0[w]; ss += red1[w]; }
        float mu = s * (1.f / 128.f);
        float var = ss * (1.f / 128.f) - mu * mu;
        stats[0] = mu; stats[1] = rsqrtf(var + 1e-5f);
    }
    __syncthreads();
    if (tid < 128)
        hns[tid] = (h1s[tid] - stats[0]) * stats[1] * g_ln[tid] + b_ln[tid];
    __syncthreads();

    // ---- h2 = gelu(hn @ W2^T + b2), 64 outputs ----
    if (tid < 64) {
        const float4* wr = (const float4*)(W2 + tid * 128);
        const float4* hr = (const float4*)hns;
        float acc = 0.f;
        #pragma unroll 8
        for (int k = 0; k < 32; k++) {
            float4 w = wr[k], h = hr[k];
            acc = fmaf(w.x, h.x, acc); acc = fmaf(w.y, h.y, acc);
            acc = fmaf(w.z, h.z, acc); acc = fmaf(w.w, h.w, acc);
        }
        h2s[tid] = gelu_f(acc + b2[tid]);
    }
    __syncthreads();

    // ---- xq = tanh(h2 @ W3^T + b3); enc = xq*pi^2; init vectors + re-upload cs ----
    if (tid < NQ) {
        const float* wr = W3 + tid * 64;
        float acc = 0.f;
        #pragma unroll
        for (int k = 0; k < 64; k++) acc = fmaf(wr[k], h2s[k], acc);
        float xqv = tanhf(acc + b3[tid]);
        float e = xqv * 9.869604401089358f;   // pi^2
        float se, ce; sincosf(0.5f * e, &se, &ce);
        // layer-0 U for this qubit
        const float* wp = qw + tid * 3;
        float w0 = wp[0], w1 = wp[1], w2v = wp[2];
        float sh, ch; sincosf(0.5f * w1, &sh, &ch);
        float sa, ca; sincosf(0.5f * (w0 + w2v), &sa, &ca);
        float sb, cb; sincosf(0.5f * (w0 - w2v), &sb, &cb);
        float2 u00 = make_float2(ch * ca, -ch * sa);
        float2 u01 = make_float2(-sh * cb, -sh * sb);
        float2 u10 = make_float2(sh * cb, -sh * sb);
        float2 u11 = make_float2(ch * ca, ch * sa);
        v0s[tid] = make_float2(u00.x * ce + u01.x * se, u00.y * ce + u01.y * se);
        v1s[tid] = make_float2(u10.x * ce + u11.x * se, u10.y * ce + u11.y * se);
        float s4, c4; sincosf(0.25f * e, &s4, &c4);
        cqs[tid] = c4; sqs[tid] = s4;
    }
    __syncthreads();

    // ---- merged gate matrices for layers 1..5 (RY re-upload folded into odd layers) ----
    if (tid < 60) {
        int L = tid / 12 + 1, q = tid - (L - 1) * 12;
        const float* wp = qw + (L * NQ + q) * 3;
        float w0 = wp[0], w1 = wp[1], w2v = wp[2];
        float sh, ch; sincosf(0.5f * w1, &sh, &ch);
        float sa, ca; sincosf(0.5f * (w0 + w2v), &sa, &ca);
        float sb, cb; sincosf(0.5f * (w0 - w2v), &sb, &cb);
        float2 U0 = make_float2(ch * ca, -ch * sa);
        float2 U1 = make_float2(-sh * cb, -sh * sb);
        float2 U2 = make_float2(sh * cb, -sh * sb);
        float2 U3 = make_float2(ch * ca, ch * sa);
        if (L & 1) {
            float cf = cqs[q], sf = sqs[q];
            float2 n0 = make_float2(U0.x * cf + U1.x * sf, U0.y * cf + U1.y * sf);
            float2 n1 = make_float2(-U0.x * sf + U1.x * cf, -U0.y * sf + U1.y * cf);
            float2 n2 = make_float2(U2.x * cf + U3.x * sf, U2.y * cf + U3.y * sf);
            float2 n3 = make_float2(-U2.x * sf + U3.x * cf, -U2.y * sf + U3.y * cf);
            U0 = n0; U1 = n1; U2 = n2; U3 = n3;
        }
        Mm[L - 1][q][0] = U0; Mm[L - 1][q][1] = U1;
        Mm[L - 1][q][2] = U2; Mm[L - 1][q][3] = U3;
    }
    __syncthreads();

    // ---- register-resident state: s[r] = amp at canonical index (r<<8)|tid ----
    float2 s[16];
    {
        float2 cm = (tid & 1) ? v1s[11] : v0s[11];
        #pragma unroll
        for (int p = 1; p < 8; p++) {
            float2 f = ((tid >> p) & 1) ? v1s[11 - p] : v0s[11 - p];
            cm = cmulc(cm, f);
        }
        #pragma unroll
        for (int r = 0; r < 16; r++) {
            float2 a = cm;
            #pragma unroll
            for (int p = 8; p < 12; p++) {
                float2 f = ((r >> (p - 8)) & 1) ? v1s[11 - p] : v0s[11 - p];
                a = cmulc(a, f);
            }
            s[r] = a;
        }
    }

    int b = 0;

    // ---- layer-0 perm RT (canonical scatter -> canonical) ----
    {
        float* re = dsm + b * 8192; float* im = re + 4096;
        #pragma unroll
        for (int r = 0; r < 16; r++) {
            int i = (r << 8) | tid;
            int d = permdst(i);
            re[d] = s[r].x; im[d] = s[r].y;
        }
        __syncthreads();
        #pragma unroll
        for (int r = 0; r < 16; r++) {
            int a = (r << 8) | tid;
            s[r] = make_float2(re[a], im[a]);
        }
        b ^= 1;
    }

    // ---- layers 1..5 ----
    for (int l = 1; l < 6; l++) {
        // gates on register bits (i bits 8..11 -> qubits 3,2,1,0)
        #pragma unroll
        for (int rb = 0; rb < 4; rb++) {
            const int q = 3 - rb;
            float2 G0 = Mm[l - 1][q][0], G1 = Mm[l - 1][q][1];
            float2 G2 = Mm[l - 1][q][2], G3 = Mm[l - 1][q][3];
            #pragma unroll
            for (int r = 0; r < 16; r++) {
                if (!((r >> rb) & 1)) {
                    const int r1 = r | (1 << rb);
                    float2 a0 = s[r], a1 = s[r1];
                    s[r]  = cmad2(G0, a0, G1, a1);
                    s[r1] = cmad2(G2, a0, G3, a1);
                }
            }
        }
        // gates on lane bits (i bits 0..4 -> qubits 11,10,9,8,7) via shuffles
        #pragma unroll
        for (int p = 0; p < 5; p++) {
            const int q = 11 - p;
            float2 G0 = Mm[l - 1][q][0], G1 = Mm[l - 1][q][1];
            float2 G2 = Mm[l - 1][q][2], G3 = Mm[l - 1][q][3];
            const int sb = (lane >> p) & 1;
            float2 Gd = sb ? G3 : G0;
            float2 Go = sb ? G2 : G1;
            #pragma unroll
            for (int r = 0; r < 16; r++) {
                float ox = __shfl_xor_sync(~0u, s[r].x, 1 << p);
                float oy = __shfl_xor_sync(~0u, s[r].y, 1 << p);
                s[r] = cmad2(Gd, s[r], Go, make_float2(ox, oy));
            }
        }
        // transpose RT: canonical -> transposed (warp bits into register bits)
        {
            float* re = dsm + b * 8192; float* im = re + 4096;
            #pragma unroll
            for (int r = 0; r < 16; r++) {
                int a = (r << 8) | tid;
                re[a] = s[r].x; im[a] = s[r].y;
            }
            __syncthreads();
            #pragma unroll
            for (int r = 0; r < 16; r++) {
                int a = tix(r, tid);
                s[r] = make_float2(re[a], im[a]);
            }
            b ^= 1;
        }
        // gates on transposed register bits (i bits 5..7 -> qubits 6,5,4)
        #pragma unroll
        for (int rb = 0; rb < 3; rb++) {
            const int q = 6 - rb;
            float2 G0 = Mm[l - 1][q][0], G1 = Mm[l - 1][q][1];
            float2 G2 = Mm[l - 1][q][2], G3 = Mm[l - 1][q][3];
            #pragma unroll
            for (int r = 0; r < 16; r++) {
                if (!((r >> rb) & 1)) {
                    const int r1 = r | (1 << rb);
                    float2 a0 = s[r], a1 = s[r1];
                    s[r]  = cmad2(G0, a0, G1, a1);
                    s[r1] = cmad2(G2, a0, G3, a1);
                }
            }
        }
        if (l < 5) {
            // perm RT: transposed scatter (+ CZ sign on odd layers) -> canonical
            const bool cz = (l & 1);
            float* re = dsm + b * 8192; float* im = re + 4096;
            #pragma unroll
            for (int r = 0; r < 16; r++) {
                int i = tix(r, tid);
                int d = permdst(i);
                float sx = s[r].x, sy = s[r].y;
                if (cz) {
                    int f = __popc((d & (d >> 2)) & 0x2AA) & 1;
                    if (f) { sx = -sx; sy = -sy; }
                }
                re[d] = sx; im[d] = sy;
            }
            __syncthreads();
            #pragma unroll
            for (int r = 0; r < 16; r++) {
                int a = (r << 8) | tid;
                s[r] = make_float2(re[a], im[a]);
            }
            b ^= 1;
        }
    }

    // ---- measurement from transposed layout, layer-5 perm folded in ----
    float z0 = 0.f, z1 = 0.f, z2 = 0.f;
    #pragma unroll
    for (int r = 0; r < 16; r++) {
        int i = tix(r, tid);
        int d = permdst(i);
        float p = s[r].x * s[r].x + s[r].y * s[r].y;
        z0 += ((d >> 11) & 1) ? -p : p;
        z1 += ((d >> 10) & 1) ? -p : p;
        z2 += ((d >> 9) & 1) ? -p : p;
    }
    #pragma unroll
    for (int o = 16; o; o >>= 1) {
        z0 += __shfl_xor_sync(~0u, z0, o);
        z1 += __shfl_xor_sync(~0u, z1, o);
        z2 += __shfl_xor_sync(~0u, z2, o);
    }
    if (lane == 0) { wz[wid][0] = z0; wz[wid][1] = z1; wz[wid][2] = z2; }
    __syncthreads();
    if (tid < 3) {
        float t = 0.f;
        #pragma unroll
        for (int w = 0; w < 8; w++) t += wz[w][tid];
        qv[tid] = t;
    }
    __syncthreads();

    // ---- head: gelu(q @ W4^T + b4) @ W5^T + b5 ----
    if (tid < 32) {
        float acc = b4[tid];
        acc = fmaf(W4[tid * 3 + 0], qv[0], acc);
        acc = fmaf(W4[tid * 3 + 1], qv[1], acc);
        acc = fmaf(W4[tid * 3 + 2], qv[2], acc);
        h4s[tid] = gelu_f(acc);
    }
    __syncthreads();
    if (tid < 64) {
        const float* wr = W5 + tid * 32;
        float acc = b5[tid];
        #pragma unroll
        for (int j = 0; j < 32; j++) acc = fmaf(wr[j], h4s[j], acc);
        out[bidx * 64 + tid] = acc;
    }
}

extern "C" void kernel_launch(void* const* d_in, const int* in_sizes, int n_in,
                              void* d_out, int out_size)
{
    const float* x    = (const float*)d_in[0];
    const float* W1   = (const float*)d_in[1];
    const float* b1   = (const float*)d_in[2];
    const float* g_ln = (const float*)d_in[3];
    const float* b_ln = (const float*)d_in[4];
    const float* W2   = (const float*)d_in[5];
    const float* b2   = (const float*)d_in[6];
    const float* W3   = (const float*)d_in[7];
    const float* b3   = (const float*)d_in[8];
    const float* qw   = (const float*)d_in[9];
    const float* W4   = (const float*)d_in[10];
    const float* b4   = (const float*)d_in[11];
    const float* W5   = (const float*)d_in[12];
    const float* b5   = (const float*)d_in[13];

    const size_t shmem = 16384 * sizeof(float);  // 64 KB: 2 SoA ping-pong buffers
    cudaFuncSetAttribute(qpu_kernel, cudaFuncAttributeMaxDynamicSharedMemorySize,
                         (int)shmem);
    qpu_kernel<<<NB, TPB, shmem>>>(x, W1, b1, g_ln, b_ln, W2, b2, W3, b3, qw,
                                   W4, b4, W5, b5, (float*)d_out);
}

// round 3
// speedup vs baseline: 1.3850x; 1.0877x over previous
#include <cuda_runtime.h>
#include <math.h>

#define NQ 12
#define TPB 256
#define NB 256

typedef unsigned long long u64;

__device__ __forceinline__ u64 pk(float lo, float hi) {
    u64 r;
    asm("mov.b64 %0,{%1,%2};" : "=l"(r)
        : "r"(__float_as_uint(lo)), "r"(__float_as_uint(hi)));
    return r;
}
__device__ __forceinline__ void upk(u64 v, float& lo, float& hi) {
    unsigned a, b;
    asm("mov.b64 {%0,%1},%2;" : "=r"(a), "=r"(b) : "l"(v));
    lo = __uint_as_float(a); hi = __uint_as_float(b);
}
__device__ __forceinline__ u64 sp(float f) { return pk(f, f); }
__device__ __forceinline__ u64 f2(u64 a, u64 b, u64 c) {
    u64 d;
    asm("fma.rn.f32x2 %0,%1,%2,%3;" : "=l"(d) : "l"(a), "l"(b), "l"(c));
    return d;
}
__device__ __forceinline__ u64 m2(u64 a, u64 b) {
    u64 d;
    asm("mul.rn.f32x2 %0,%1,%2;" : "=l"(d) : "l"(a), "l"(b));
    return d;
}
__device__ __forceinline__ u64 swp(u64 v) {
    float l, h; upk(v, l, h); return pk(h, l);
}

__device__ __forceinline__ float2 cmulc(float2 x, float2 y) {
    return make_float2(x.x * y.x - x.y * y.y, x.x * y.y + x.y * y.x);
}

__device__ __forceinline__ float gelu_f(float x) {
    return 0.5f * x * (1.0f + erff(x * 0.7071067811865476f));
}

// Composed CNOT-ring permutation (CNOT(0,1)..CNOT(10,11),CNOT(11,0)).
// Qubit w lives at bit position (11-w).
__device__ __forceinline__ int permdst(int idx) {
    int y = idx;
    y ^= y >> 1; y ^= y >> 2; y ^= y >> 4; y ^= y >> 8;
    return (y & 0x7FF) | (((y ^ (idx >> 11)) & 1) << 11);
}

// transposed layout, low 11 bits (bit 11 = pack lane, handled separately):
// bits {0..4}=lane, {5..7}=k bits 0..2, {8..10}=warp
__device__ __forceinline__ int tixlow(int k, int tid) {
    return (tid & 31) | ((k & 7) << 5) | ((tid >> 5) << 8);
}

// vectorized 2x2 complex gate on a packed pair (each u64 = 2 independent amps)
__device__ __forceinline__ void vgate(u64& X0, u64& Y0, u64& X1, u64& Y1,
    u64 g0x, u64 g0y, u64 g0yn, u64 g1x, u64 g1y, u64 g1yn,
    u64 g2x, u64 g2y, u64 g2yn, u64 g3x, u64 g3y, u64 g3yn)
{
    u64 nX0 = f2(g1yn, Y1, f2(g1x, X1, f2(g0yn, Y0, m2(g0x, X0))));
    u64 nY0 = f2(g1y,  X1, f2(g1x, Y1, f2(g0y,  X0, m2(g0x, Y0))));
    u64 nX1 = f2(g3yn, Y1, f2(g3x, X1, f2(g2yn, Y0, m2(g2x, X0))));
    u64 nY1 = f2(g3y,  X1, f2(g3x, Y1, f2(g2y,  X0, m2(g2x, Y0))));
    X0 = nX0; Y0 = nY0; X1 = nX1; Y1 = nY1;
}

__global__ void __launch_bounds__(TPB, 2)
qpu_kernel(const float* __restrict__ x,
           const float* __restrict__ W1, const float* __restrict__ b1,
           const float* __restrict__ g_ln, const float* __restrict__ b_ln,
           const float* __restrict__ W2, const float* __restrict__ b2,
           const float* __restrict__ W3, const float* __restrict__ b3,
           const float* __restrict__ qw,
           const float* __restrict__ W4, const float* __restrict__ b4,
           const float* __restrict__ W5, const float* __restrict__ b5,
           float* __restrict__ out)
{
    // dynamic: 2 ping-pong buffers, each (4096 re + 4096 im) floats = 64 KB
    extern __shared__ float dsm[];
    __shared__ __align__(16) float xrow[256];
    __shared__ __align__(16) float h1s[128];
    __shared__ __align__(16) float hns[128];
    __shared__ __align__(16) float h2s[64];
    __shared__ float2 Mm[5][NQ][4];       // merged gate matrices, layers 1..5
    __shared__ float2 v0s[NQ], v1s[NQ];   // initial per-qubit product-state vectors
    __shared__ float cqs[NQ], sqs[NQ];    // re-upload RY half-angle cos/sin
    __shared__ float red0[8], red1[8];
    __shared__ float stats[2];
    __shared__ float wz[8][3];
    __shared__ float qv[3];
    __shared__ float h4s[32];

    const int tid = threadIdx.x;
    const int bidx = blockIdx.x;
    const int lane = tid & 31, wid = tid >> 5;

    xrow[tid] = x[bidx * 256 + tid];
    __syncthreads();

    // ---- h1 = gelu(x @ W1^T + b1), 128 outputs ----
    if (tid < 128) {
        const float4* wr = (const float4*)(W1 + tid * 256);
        const float4* xr = (const float4*)xrow;
        float acc0 = 0.f, acc1 = 0.f;
        #pragma unroll 8
        for (int k = 0; k < 64; k += 2) {
            float4 w = wr[k], xv = xr[k];
            acc0 = fmaf(w.x, xv.x, acc0); acc0 = fmaf(w.y, xv.y, acc0);
            acc0 = fmaf(w.z, xv.z, acc0); acc0 = fmaf(w.w, xv.w, acc0);
            float4 w2_ = wr[k + 1], xv2 = xr[k + 1];
            acc1 = fmaf(w2_.x, xv2.x, acc1); acc1 = fmaf(w2_.y, xv2.y, acc1);
            acc1 = fmaf(w2_.z, xv2.z, acc1); acc1 = fmaf(w2_.w, xv2.w, acc1);
        }
        h1s[tid] = gelu_f(acc0 + acc1 + b1[tid]);
    }
    __syncthreads();

    // ---- layernorm over 128 ----
    {
        float v = (tid < 128) ? h1s[tid] : 0.f;
        float s = v, ss = v * v;
        #pragma unroll
        for (int o = 16; o; o >>= 1) {
            s += __shfl_xor_sync(~0u, s, o);
            ss += __shfl_xor_sync(~0u, ss, o);
        }
        if (lane == 0) { red0[wid] = s; red1[wid] = ss; }
    }
    __syncthreads();
    if (tid == 0) {
        float s = 0.f, ss = 0.f;
        #pragma unroll
        for (int w = 0; w < 8; w++) { s += red0[w]; ss += red1[w]; }
        float mu = s * (1.f / 128.f);
        float var = ss * (1.f / 128.f) - mu * mu;
        stats[0] = mu; stats[1] = rsqrtf(var + 1e-5f);
    }
    __syncthreads();
    if (tid < 128)
        hns[tid] = (h1s[tid] - stats[0]) * stats[1] * g_ln[tid] + b_ln[tid];
    __syncthreads();

    // ---- h2 = gelu(hn @ W2^T + b2), 64 outputs ----
    if (tid < 64) {
        const float4* wr = (const float4*)(W2 + tid * 128);
        const float4* hr = (const float4*)hns;
        float acc = 0.f;
        #pragma unroll 8
        for (int k = 0; k < 32; k++) {
            float4 w = wr[k], h = hr[k];
            acc = fmaf(w.x, h.x, acc); acc = fmaf(w.y, h.y, acc);
            acc = fmaf(w.z, h.z, acc); acc = fmaf(w.w, h.w, acc);
        }
        h2s[tid] = gelu_f(acc + b2[tid]);
    }
    __syncthreads();

    // ---- xq = tanh(h2 @ W3^T + b3); enc = xq*pi^2; init vectors + re-upload cs ----
    if (tid < NQ) {
        const float* wr = W3 + tid * 64;
        float acc = 0.f;
        #pragma unroll
        for (int k = 0; k < 64; k++) acc = fmaf(wr[k], h2s[k], acc);
        float xqv = tanhf(acc + b3[tid]);
        float e = xqv * 9.869604401089358f;   // pi^2
        float se, ce; sincosf(0.5f * e, &se, &ce);
        const float* wp = qw + tid * 3;
        float w0 = wp[0], w1 = wp[1], w2v = wp[2];
        float sh, ch; sincosf(0.5f * w1, &sh, &ch);
        float sa, ca; sincosf(0.5f * (w0 + w2v), &sa, &ca);
        float sb, cb; sincosf(0.5f * (w0 - w2v), &sb, &cb);
        float2 u00 = make_float2(ch * ca, -ch * sa);
        float2 u01 = make_float2(-sh * cb, -sh * sb);
        float2 u10 = make_float2(sh * cb, -sh * sb);
        float2 u11 = make_float2(ch * ca, ch * sa);
        v0s[tid] = make_float2(u00.x * ce + u01.x * se, u00.y * ce + u01.y * se);
        v1s[tid] = make_float2(u10.x * ce + u11.x * se, u10.y * ce + u11.y * se);
        float s4, c4; sincosf(0.25f * e, &s4, &c4);
        cqs[tid] = c4; sqs[tid] = s4;
    }
    __syncthreads();

    // ---- merged gate matrices for layers 1..5 ----
    if (tid < 60) {
        int L = tid / 12 + 1, q = tid - (L - 1) * 12;
        const float* wp = qw + (L * NQ + q) * 3;
        float w0 = wp[0], w1 = wp[1], w2v = wp[2];
        float sh, ch; sincosf(0.5f * w1, &sh, &ch);
        float sa, ca; sincosf(0.5f * (w0 + w2v), &sa, &ca);
        float sb, cb; sincosf(0.5f * (w0 - w2v), &sb, &cb);
        float2 U0 = make_float2(ch * ca, -ch * sa);
        float2 U1 = make_float2(-sh * cb, -sh * sb);
        float2 U2 = make_float2(sh * cb, -sh * sb);
        float2 U3 = make_float2(ch * ca, ch * sa);
        if (L & 1) {
            float cf = cqs[q], sf = sqs[q];
            float2 n0 = make_float2(U0.x * cf + U1.x * sf, U0.y * cf + U1.y * sf);
            float2 n1 = make_float2(-U0.x * sf + U1.x * cf, -U0.y * sf + U1.y * cf);
            float2 n2 = make_float2(U2.x * cf + U3.x * sf, U2.y * cf + U3.y * sf);
            float2 n3 = make_float2(-U2.x * sf + U3.x * cf, -U2.y * sf + U3.y * cf);
            U0 = n0; U1 = n1; U2 = n2; U3 = n3;
        }
        Mm[L - 1][q][0] = U0; Mm[L - 1][q][1] = U1;
        Mm[L - 1][q][2] = U2; Mm[L - 1][q][3] = U3;
    }
    __syncthreads();

    // ---- packed register state: SX[k]/SY[k] hold amps at index (k<<8)|tid
    //      (lo lane) and (k<<8)|tid|0x800 (hi lane); pack lane = idx bit 11 = qubit 0
    u64 SX[8], SY[8];
    {
        float2 cm = (tid & 1) ? v1s[11] : v0s[11];
        #pragma unroll
        for (int p = 1; p < 8; p++) {
            float2 f = ((tid >> p) & 1) ? v1s[11 - p] : v0s[11 - p];
            cm = cmulc(cm, f);
        }
        float2 q0a = v0s[0], q0b = v1s[0];
        #pragma unroll
        for (int k = 0; k < 8; k++) {
            float2 a = cm;
            #pragma unroll
            for (int p = 8; p < 11; p++) {
                float2 f = ((k >> (p - 8)) & 1) ? v1s[11 - p] : v0s[11 - p];
                a = cmulc(a, f);
            }
            float2 lo = cmulc(a, q0a);
            float2 hi = cmulc(a, q0b);
            SX[k] = pk(lo.x, hi.x);
            SY[k] = pk(lo.y, hi.y);
        }
    }

    int b = 0;

    // ---- layer-0 perm RT (canonical scatter -> canonical gather) ----
    {
        float* re = dsm + b * 8192; float* im = re + 4096;
        #pragma unroll
        for (int k = 0; k < 8; k++) {
            int i0 = (k << 8) | tid;
            int d0 = permdst(i0);
            int d1 = d0 ^ 0x7FF;
            float xl, xh, yl, yh;
            upk(SX[k], xl, xh); upk(SY[k], yl, yh);
            re[d0] = xl; im[d0] = yl;
            re[d1] = xh; im[d1] = yh;
        }
        __syncthreads();
        #pragma unroll
        for (int k = 0; k < 8; k++) {
            int a0 = (k << 8) | tid;
            SX[k] = pk(re[a0], re[a0 + 2048]);
            SY[k] = pk(im[a0], im[a0 + 2048]);
        }
        b ^= 1;
    }

    // ---- layers 1..5 ----
    for (int l = 1; l < 6; l++) {
        const float2* M = &Mm[l - 1][0][0];

        // gates on canonical k-bits 0..2 (idx bits 8..10 -> qubits 3,2,1)
        #pragma unroll
        for (int rb = 0; rb < 3; rb++) {
            const int q = 3 - rb;
            float2 G0 = M[q * 4 + 0], G1 = M[q * 4 + 1];
            float2 G2 = M[q * 4 + 2], G3 = M[q * 4 + 3];
            u64 g0x = sp(G0.x), g0y = sp(G0.y), g0yn = sp(-G0.y);
            u64 g1x = sp(G1.x), g1y = sp(G1.y), g1yn = sp(-G1.y);
            u64 g2x = sp(G2.x), g2y = sp(G2.y), g2yn = sp(-G2.y);
            u64 g3x = sp(G3.x), g3y = sp(G3.y), g3yn = sp(-G3.y);
            #pragma unroll
            for (int k = 0; k < 8; k++) {
                if (!((k >> rb) & 1)) {
                    const int k1 = k | (1 << rb);
                    vgate(SX[k], SY[k], SX[k1], SY[k1],
                          g0x, g0y, g0yn, g1x, g1y, g1yn,
                          g2x, g2y, g2yn, g3x, g3y, g3yn);
                }
            }
        }
        // gate on pack lane (idx bit 11 -> qubit 0): in-register half-swap
        {
            float2 G0 = M[0], G1 = M[1], G2 = M[2], G3 = M[3];
            u64 Dx = pk(G0.x, G3.x), Dy = pk(G0.y, G3.y), Dyn = pk(-G0.y, -G3.y);
            u64 Ox = pk(G1.x, G2.x), Oy = pk(G1.y, G2.y), Oyn = pk(-G1.y, -G2.y);
            #pragma unroll
            for (int k = 0; k < 8; k++) {
                u64 sX = swp(SX[k]), sY = swp(SY[k]);
                u64 nX = f2(Oyn, sY, f2(Ox, sX, f2(Dyn, SY[k], m2(Dx, SX[k]))));
                u64 nY = f2(Oy,  sX, f2(Ox, sY, f2(Dy,  SX[k], m2(Dx, SY[k]))));
                SX[k] = nX; SY[k] = nY;
            }
        }
        // gates on lane bits (idx bits 0..4 -> qubits 11..7) via shuffles
        #pragma unroll
        for (int p = 0; p < 5; p++) {
            const int q = 11 - p;
            float2 G0 = M[q * 4 + 0], G1 = M[q * 4 + 1];
            float2 G2 = M[q * 4 + 2], G3 = M[q * 4 + 3];
            const int sb = (lane >> p) & 1;
            float2 Gd = sb ? G3 : G0;
            float2 Go = sb ? G2 : G1;
            u64 gdx = sp(Gd.x), gdy = sp(Gd.y), gdyn = sp(-Gd.y);
            u64 gox = sp(Go.x), goy = sp(Go.y), goyn = sp(-Go.y);
            #pragma unroll
            for (int k = 0; k < 8; k++) {
                float xl, xh, yl, yh;
                upk(SX[k], xl, xh); upk(SY[k], yl, yh);
                float oxl = __shfl_xor_sync(~0u, xl, 1 << p);
                float oxh = __shfl_xor_sync(~0u, xh, 1 << p);
                float oyl = __shfl_xor_sync(~0u, yl, 1 << p);
                float oyh = __shfl_xor_sync(~0u, yh, 1 << p);
                u64 OX = pk(oxl, oxh), OY = pk(oyl, oyh);
                u64 nX = f2(goyn, OY, f2(gox, OX, f2(gdyn, SY[k], m2(gdx, SX[k]))));
                u64 nY = f2(goy,  OX, f2(gox, OY, f2(gdy,  SX[k], m2(gdx, SY[k]))));
                SX[k] = nX; SY[k] = nY;
            }
        }
        // transpose RT (64-bit smem ops; pack-partner-adjacent layout)
        {
            u64* re64 = (u64*)(dsm + b * 8192);
            u64* im64 = (u64*)(dsm + b * 8192 + 4096);
            #pragma unroll
            for (int k = 0; k < 8; k++) {
                int a0 = (k << 8) | tid;
                re64[a0] = SX[k]; im64[a0] = SY[k];
            }
            __syncthreads();
            #pragma unroll
            for (int k = 0; k < 8; k++) {
                int j = tixlow(k, tid);
                SX[k] = re64[j]; SY[k] = im64[j];
            }
            b ^= 1;
        }
        // gates on transposed k-bits 0..2 (idx bits 5..7 -> qubits 6,5,4)
        #pragma unroll
        for (int rb = 0; rb < 3; rb++) {
            const int q = 6 - rb;
            float2 G0 = M[q * 4 + 0], G1 = M[q * 4 + 1];
            float2 G2 = M[q * 4 + 2], G3 = M[q * 4 + 3];
            u64 g0x = sp(G0.x), g0y = sp(G0.y), g0yn = sp(-G0.y);
            u64 g1x = sp(G1.x), g1y = sp(G1.y), g1yn = sp(-G1.y);
            u64 g2x = sp(G2.x), g2y = sp(G2.y), g2yn = sp(-G2.y);
            u64 g3x = sp(G3.x), g3y = sp(G3.y), g3yn = sp(-G3.y);
            #pragma unroll
            for (int k = 0; k < 8; k++) {
                if (!((k >> rb) & 1)) {
                    const int k1 = k | (1 << rb);
                    vgate(SX[k], SY[k], SX[k1], SY[k1],
                          g0x, g0y, g0yn, g1x, g1y, g1yn,
                          g2x, g2y, g2yn, g3x, g3y, g3yn);
                }
            }
        }
        if (l < 5) {
            // perm RT: transposed scatter (+ CZ sign on odd layers) -> canonical
            const bool cz = (l & 1);
            float* re = dsm + b * 8192; float* im = re + 4096;
            #pragma unroll
            for (int k = 0; k < 8; k++) {
                int i0 = tixlow(k, tid);
                int d0 = permdst(i0);
                int d1 = d0 ^ 0x7FF;
                float xl, xh, yl, yh;
                upk(SX[k], xl, xh); upk(SY[k], yl, yh);
                if (cz) {
                    unsigned s0 = ((unsigned)__popc((d0 & (d0 >> 2)) & 0x2AA) & 1u) << 31;
                    unsigned s1 = ((unsigned)__popc((d1 & (d1 >> 2)) & 0x2AA) & 1u) << 31;
                    xl = __uint_as_float(__float_as_uint(xl) ^ s0);
                    yl = __uint_as_float(__float_as_uint(yl) ^ s0);
                    xh = __uint_as_float(__float_as_uint(xh) ^ s1);
                    yh = __uint_as_float(__float_as_uint(yh) ^ s1);
                }
                re[d0] = xl; im[d0] = yl;
                re[d1] = xh; im[d1] = yh;
            }
            __syncthreads();
            #pragma unroll
            for (int k = 0; k < 8; k++) {
                int a0 = (k << 8) | tid;
                SX[k] = pk(re[a0], re[a0 + 2048]);
                SY[k] = pk(im[a0], im[a0 + 2048]);
            }
            b ^= 1;
        }
    }

    // ---- measurement from transposed layout, layer-5 perm folded in ----
    float z0 = 0.f, z1 = 0.f, z2 = 0.f;
    #pragma unroll
    for (int k = 0; k < 8; k++) {
        u64 P = f2(SY[k], SY[k], m2(SX[k], SX[k]));
        float pl, ph; upk(P, pl, ph);
        int i0 = tixlow(k, tid);
        int d0 = permdst(i0);
        // partner dst = d0 ^ 0x7FF: bit 11 equal, bits 10/9 complemented
        float s = pl + ph, dd = pl - ph;
        z0 += ((d0 >> 11) & 1) ? -s : s;
        z1 += ((d0 >> 10) & 1) ? -dd : dd;
        z2 += ((d0 >> 9) & 1) ? -dd : dd;
    }
    #pragma unroll
    for (int o = 16; o; o >>= 1) {
        z0 += __shfl_xor_sync(~0u, z0, o);
        z1 += __shfl_xor_sync(~0u, z1, o);
        z2 += __shfl_xor_sync(~0u, z2, o);
    }
    if (lane == 0) { wz[wid][0] = z0; wz[wid][1] = z1; wz[wid][2] = z2; }
    __syncthreads();
    if (tid < 3) {
        float t = 0.f;
        #pragma unroll
        for (int w = 0; w < 8; w++) t += wz[w][tid];
        qv[tid] = t;
    }
    __syncthreads();

    // ---- head: gelu(q @ W4^T + b4) @ W5^T + b5 ----
    if (tid < 32) {
        float acc = b4[tid];
        acc = fmaf(W4[tid * 3 + 0], qv[0], acc);
        acc = fmaf(W4[tid * 3 + 1], qv[1], acc);
        acc = fmaf(W4[tid * 3 + 2], qv[2], acc);
        h4s[tid] = gelu_f(acc);
    }
    __syncthreads();
    if (tid < 64) {
        const float* wr = W5 + tid * 32;
        float acc = b5[tid];
        #pragma unroll
        for (int j = 0; j < 32; j++) acc = fmaf(wr[j], h4s[j], acc);
        out[bidx * 64 + tid] = acc;
    }
}

extern "C" void kernel_launch(void* const* d_in, const int* in_sizes, int n_in,
                              void* d_out, int out_size)
{
    const float* x    = (const float*)d_in[0];
    const float* W1   = (const float*)d_in[1];
    const float* b1   = (const float*)d_in[2];
    const float* g_ln = (const float*)d_in[3];
    const float* b_ln = (const float*)d_in[4];
    const float* W2   = (const float*)d_in[5];
    const float* b2   = (const float*)d_in[6];
    const float* W3   = (const float*)d_in[7];
    const float* b3   = (const float*)d_in[8];
    const float* qw   = (const float*)d_in[9];
    const float* W4   = (const float*)d_in[10];
    const float* b4   = (const float*)d_in[11];
    const float* W5   = (const float*)d_in[12];
    const float* b5   = (const float*)d_in[13];

    const size_t shmem = 16384 * sizeof(float);  // 64 KB: 2 ping-pong buffers
    cudaFuncSetAttribute(qpu_kernel, cudaFuncAttributeMaxDynamicSharedMemorySize,
                         (int)shmem);
    qpu_kernel<<<NB, TPB, shmem>>>(x, W1, b1, g_ln, b_ln, W2, b2, W3, b3, qw,
                                   W4, b4, W5, b5, (float*)d_out);
}